// round 14
// baseline (speedup 1.0000x reference)
#include <cuda_runtime.h>
#include <cuda_fp16.h>
#include <cstdint>

#define NTOK 197
#define CIN 384
#define COUT 1152
#define TT 8
#define OUT_BT_STRIDE (COUT * NTOK)

__device__ float g_rf[32 * 4];
__device__ float g_r[256 * COUT];
__device__ uint4 g_wh4[COUT * CIN / 8];   // weight fp16, [o][k] row-major
__device__ float g_mw[4 * 3 * COUT * CIN]; // moe_w transposed: [e][k][o][c]

// ======================= helpers =======================
__device__ __forceinline__ uint32_t smem_u32(const void* p) {
    uint32_t a;
    asm("{ .reg .u64 t; cvta.to.shared.u64 t, %1; cvt.u32.u64 %0, t; }" : "=r"(a) : "l"(p));
    return a;
}
__device__ __forceinline__ uint32_t hsplit2(float a, float b, uint32_t& lo) {
    __half2 h = __floats2half2_rn(a, b);
    float2 hf = __half22float2(h);
    __half2 l = __floats2half2_rn(a - hf.x, b - hf.y);
    lo = *reinterpret_cast<uint32_t*>(&l);
    return *reinterpret_cast<uint32_t*>(&h);
}
__device__ __forceinline__ uint32_t h2pack(float a, float b) {
    __half2 h = __floats2half2_rn(a, b);
    return *reinterpret_cast<uint32_t*>(&h);
}
#define STS128(a, v0, v1, v2, v3) \
    asm volatile("st.shared.v4.b32 [%0], {%1, %2, %3, %4};" :: "r"(a), "r"(v0), "r"(v1), "r"(v2), "r"(v3) : "memory")
#define CP16(dst, src) \
    asm volatile("cp.async.cg.shared.global [%0], [%1], 16;" :: "r"(dst), "l"(src) : "memory")
#define CP_COMMIT() asm volatile("cp.async.commit_group;" ::: "memory")
#define CP_WAIT2() asm volatile("cp.async.wait_group 2;" ::: "memory")
#define LDSM4(r, a)                                                                   \
    asm volatile("ldmatrix.sync.aligned.m8n8.x4.shared.b16 {%0,%1,%2,%3}, [%4];"      \
        : "=r"((r)[0]), "=r"((r)[1]), "=r"((r)[2]), "=r"((r)[3]) : "r"(a))
#define MMA16816(d, a, b0, b1)                                                        \
    asm("mma.sync.aligned.m16n8k16.row.col.f32.f16.f16.f32 "                          \
        "{%0,%1,%2,%3}, {%4,%5,%6,%7}, {%8,%9}, {%0,%1,%2,%3};"                       \
        : "+f"((d)[0]), "+f"((d)[1]), "+f"((d)[2]), "+f"((d)[3])                      \
        : "r"((a)[0]), "r"((a)[1]), "r"((a)[2]), "r"((a)[3]), "r"(b0), "r"(b1))

// ============ Kernel 0: weight fp16 convert + moe_w transpose ============
// blocks 0..215: weight -> g_wh4.  blocks 216+: moe_w [e][o][c][k] -> g_mw [e][k][o][c]
__global__ void k_prep(const float* __restrict__ w, const float* __restrict__ moe_w) {
    if (blockIdx.x < 216) {
        int i = blockIdx.x * 256 + threadIdx.x;
        const float4 v0 = reinterpret_cast<const float4*>(w)[i * 2];
        const float4 v1 = reinterpret_cast<const float4*>(w)[i * 2 + 1];
        g_wh4[i] = make_uint4(h2pack(v0.x, v0.y), h2pack(v0.z, v0.w),
                              h2pack(v1.x, v1.y), h2pack(v1.z, v1.w));
    } else {
        // 5308416 elements / (256 thr * 4) = 5184 blocks
        int j = (blockIdx.x - 216) * 1024 + threadIdx.x * 4;
        #pragma unroll
        for (int u = 0; u < 4; ++u) {
            int jj = j + u;                       // output idx: ((e*3+k)*COUT+o)*CIN+c
            int c = jj % CIN;
            int t2 = jj / CIN;
            int o = t2 % COUT;
            int ek = t2 / COUT;
            int e = ek / 3, k = ek - e * 3;
            g_mw[jj] = moe_w[((size_t)(e * COUT + o) * CIN + c) * 3 + k];
        }
    }
}

// ======================= Kernel 1: rf =======================
__global__ void k_rf(const float* __restrict__ x, const float* __restrict__ rf_w,
                     const float* __restrict__ rf_b) {
    const int b = blockIdx.x;
    const int tid = threadIdx.x;
    float a0 = 0.f, a1 = 0.f, a2 = 0.f, a3 = 0.f;
    for (int c = tid; c < CIN; c += 128) {
        float p = 0.f;
        #pragma unroll
        for (int t = 0; t < TT; ++t)
            p += x[(size_t)(b * TT + t) * NTOK * CIN + c];
        p *= 0.125f;
        a0 += p * rf_w[0 * CIN + c];
        a1 += p * rf_w[1 * CIN + c];
        a2 += p * rf_w[2 * CIN + c];
        a3 += p * rf_w[3 * CIN + c];
    }
    __shared__ float red[4][128];
    red[0][tid] = a0; red[1][tid] = a1; red[2][tid] = a2; red[3][tid] = a3;
    __syncthreads();
    for (int s = 64; s > 0; s >>= 1) {
        if (tid < s) {
            red[0][tid] += red[0][tid + s];
            red[1][tid] += red[1][tid + s];
            red[2][tid] += red[2][tid + s];
            red[3][tid] += red[3][tid + s];
        }
        __syncthreads();
    }
    if (tid < 4) g_rf[b * 4 + tid] = red[tid][0] + rf_b[tid];
}

// ======================= Kernel 2: routing (coalesced moe_w) =======================
__global__ __launch_bounds__(256) void k_routing(const float* __restrict__ x,
                                                 const float* __restrict__ moe_b) {
    extern __shared__ float rsm[];            // clsp[4][384][10]
    __shared__ float srf[16];
    const int tid = threadIdx.x, lane = tid & 31, wid = tid >> 5;
    const int o = blockIdx.x * 8 + wid;
    const int b0 = blockIdx.y * 4;

    if (tid < 16) srf[tid] = g_rf[(b0 + (tid >> 2)) * 4 + (tid & 3)];
    #pragma unroll 1
    for (int it = 0; it < 48; ++it) {
        int e = it * 256 + tid;
        int bi = e / 3072;
        int r2 = e - bi * 3072;
        int t = r2 / CIN;
        int c = r2 - t * CIN;
        rsm[bi * 3840 + c * 10 + t + 1] =
            x[(size_t)((b0 + bi) * TT + t) * NTOK * CIN + c];
    }
    #pragma unroll 1
    for (int it = 0; it < 12; ++it) {
        int e = it * 256 + tid;
        int bi = e / 768;
        int r2 = e - bi * 768;
        int c = r2 >> 1;
        rsm[bi * 3840 + c * 10 + (r2 & 1) * 9] = 0.f;
    }
    __syncthreads();

    float f[16];
    #pragma unroll
    for (int i = 0; i < 16; ++i) f[i] = srf[i];

    float vals[32];
    #pragma unroll
    for (int i = 0; i < 32; ++i) vals[i] = 0.f;

    // 12 coalesced base pointers: g_mw[((e*3+k)*COUT+o)*CIN + c]
    const float* wb[12];
    #pragma unroll
    for (int ek = 0; ek < 12; ++ek)
        wb[ek] = g_mw + (size_t)(ek * COUT + o) * CIN + lane;

    #pragma unroll 1
    for (int ci = 0; ci < 12; ++ci) {
        const int c = ci * 32;
        float w[4][3];
        #pragma unroll
        for (int e = 0; e < 4; ++e)
            #pragma unroll
            for (int k = 0; k < 3; ++k)
                w[e][k] = wb[e * 3 + k][c];   // fully coalesced (lane=c)
        #pragma unroll
        for (int bi = 0; bi < 4; ++bi) {
            const float f0 = f[bi * 4 + 0], f1 = f[bi * 4 + 1];
            const float f2 = f[bi * 4 + 2], f3 = f[bi * 4 + 3];
            const float wv0 = f0 * w[0][0] + f1 * w[1][0] + f2 * w[2][0] + f3 * w[3][0];
            const float wv1 = f0 * w[0][1] + f1 * w[1][1] + f2 * w[2][1] + f3 * w[3][1];
            const float wv2 = f0 * w[0][2] + f1 * w[1][2] + f2 * w[2][2] + f3 * w[3][2];
            const float* cl = rsm + bi * 3840 + (c + lane) * 10;
            float cv[10];
            #pragma unroll
            for (int t = 0; t < 10; ++t) cv[t] = cl[t];
            #pragma unroll
            for (int t = 0; t < TT; ++t)
                vals[bi * 8 + t] += wv0 * cv[t] + wv1 * cv[t + 1] + wv2 * cv[t + 2];
        }
    }

    int cnt = 32;
    #pragma unroll
    for (int off = 16; off; off >>= 1) {
        cnt >>= 1;
        #pragma unroll 16
        for (int j = 0; j < cnt; ++j) {
            const float send = (lane & off) ? vals[j] : vals[j + cnt];
            const float other = __shfl_xor_sync(0xffffffffu, send, off);
            vals[j] = ((lane & off) ? vals[j + cnt] : vals[j]) + other;
        }
    }
    {
        const int bi = lane >> 3, t = lane & 7;
        float bo = 1.0f;
        #pragma unroll
        for (int e = 0; e < 4; ++e) bo += f[bi * 4 + e] * moe_b[e * COUT + o];
        g_r[(size_t)((b0 + bi) * TT + t) * COUT + o] = vals[0] + bo;
    }
}

// ======================= Kernel 3: main mma.sync GEMM (R12, unchanged) =======================
#define A_STRIDE 32768
#define OFF_B 65536
#define B_STRIDE 16384
#define OFF_SR 131072
#define SMEM_MAIN (OFF_SR + 3072 + 1024)

__global__ __launch_bounds__(512, 1) void k_main(const float* __restrict__ x,
                                                 const float* __restrict__ bias,
                                                 float* __restrict__ out) {
    extern __shared__ char dsm[];
    const uint32_t sb = (smem_u32(dsm) + 1023u) & ~1023u;
    char* dsm_al = dsm + (sb - smem_u32(dsm));
    float* sr = reinterpret_cast<float*>(dsm_al + OFF_SR);
    const int tid = threadIdx.x, lane = tid & 31, wid = tid >> 5;
    const int oBase = blockIdx.x * 128;
    const int s = blockIdx.x / 3;
    const int mBase = blockIdx.y * 128;
    const int bt0 = mBase / NTOK;
    const int bt1 = (mBase + 127) / NTOK;

    const int arow = tid >> 2;
    const int aq = tid & 3;
    const int am = mBase + arow;
    const int abt = am / NTOK;
    const float* axp = x + (size_t)am * CIN + aq * 16;
    const float* srow = sr + (abt != bt0 ? 384 : 0) + aq * 16;

    uint32_t sA[2];
    {
        const uint32_t xm = (uint32_t)(arow & 7) * 16;
        #pragma unroll
        for (int g = 0; g < 2; ++g)
            sA[g] = (uint32_t)arow * 128 + (((uint32_t)(aq * 32 + g * 16)) ^ xm);
    }

    const int wm = (wid & 3) * 32;
    const int wn = (wid >> 2) * 32;

    const int lrow = lane & 15, lkh = lane >> 4;
    uint32_t aBase[2], aXm[2], bBase[2], bXm[2];
    #pragma unroll
    for (int mt = 0; mt < 2; ++mt) {
        const int row = wm + mt * 16 + lrow;
        aBase[mt] = (uint32_t)row * 128;
        aXm[mt] = (uint32_t)(row & 7) * 16;
    }
    #pragma unroll
    for (int nt = 0; nt < 2; ++nt) {
        const int row = wn + nt * 16 + lrow;
        bBase[nt] = (uint32_t)row * 128;
        bXm[nt] = (uint32_t)(row & 7) * 16;
    }

    float acc[2][4][4];
    #pragma unroll
    for (int i = 0; i < 2; ++i)
        #pragma unroll
        for (int j = 0; j < 4; ++j)
            #pragma unroll
            for (int e = 0; e < 4; ++e) acc[i][j][e] = 0.f;

    float4 xr[4];

    auto ldgA = [&](int kOff) {
        const float4* xp4 = reinterpret_cast<const float4*>(axp + kOff);
        #pragma unroll
        for (int i = 0; i < 4; ++i) xr[i] = xp4[i];
    };
    auto stsA = [&](int kOff, int buf) {
        const float4* rp4 = reinterpret_cast<const float4*>(srow + kOff);
        const uint32_t aH = sb + buf * A_STRIDE;
        #pragma unroll
        for (int g = 0; g < 2; ++g) {
            const float4 xa = xr[2 * g], xb = xr[2 * g + 1];
            const float4 ra = rp4[2 * g], rb = rp4[2 * g + 1];
            uint32_t h[4], l[4];
            h[0] = hsplit2(xa.x * ra.x, xa.y * ra.y, l[0]);
            h[1] = hsplit2(xa.z * ra.z, xa.w * ra.w, l[1]);
            h[2] = hsplit2(xb.x * rb.x, xb.y * rb.y, l[2]);
            h[3] = hsplit2(xb.z * rb.z, xb.w * rb.w, l[3]);
            STS128(aH + sA[g], h[0], h[1], h[2], h[3]);
            STS128(aH + sA[g] + 16384, l[0], l[1], l[2], l[3]);
        }
    };
    auto ldB = [&](int kOff, int buf) {
        const uint32_t bH = sb + OFF_B + buf * B_STRIDE;
        const char* gh = (const char*)g_wh4;
        #pragma unroll
        for (int it = 0; it < 2; ++it) {
            const int idx = it * 512 + tid;
            const int ol = idx >> 3;
            const int kq = idx & 7;
            const size_t gb = ((size_t)(oBase + ol) * CIN + kOff + kq * 8) * 2;
            const uint32_t off = (uint32_t)(ol * 128) +
                                 (((uint32_t)(kq * 16)) ^ ((uint32_t)(ol & 7) * 16));
            CP16(bH + off, gh + gb);
        }
    };
    auto compute = [&](int bufA, int bufB) {
        const uint32_t baseA = sb + bufA * A_STRIDE;
        const uint32_t baseB = sb + OFF_B + bufB * B_STRIDE;
        #pragma unroll
        for (int kk = 0; kk < 4; ++kk) {
            const uint32_t kbl = (uint32_t)(kk * 32 + lkh * 16);
            uint32_t Ah[2][4], Al[2][4], Bh[2][4];
            #pragma unroll
            for (int mt = 0; mt < 2; ++mt) {
                const uint32_t ad = baseA + aBase[mt] + (kbl ^ aXm[mt]);
                LDSM4(Ah[mt], ad);
                LDSM4(Al[mt], ad + 16384);
            }
            #pragma unroll
            for (int nt = 0; nt < 2; ++nt) {
                const uint32_t bd = baseB + bBase[nt] + (kbl ^ bXm[nt]);
                LDSM4(Bh[nt], bd);
            }
            #pragma unroll
            for (int nt = 0; nt < 2; ++nt)
                #pragma unroll
                for (int mt = 0; mt < 2; ++mt) {
                    MMA16816(acc[mt][nt * 2],     Ah[mt], Bh[nt][0], Bh[nt][2]);
                    MMA16816(acc[mt][nt * 2 + 1], Ah[mt], Bh[nt][1], Bh[nt][3]);
                }
            #pragma unroll
            for (int nt = 0; nt < 2; ++nt)
                #pragma unroll
                for (int mt = 0; mt < 2; ++mt) {
                    MMA16816(acc[mt][nt * 2],     Al[mt], Bh[nt][0], Bh[nt][2]);
                    MMA16816(acc[mt][nt * 2 + 1], Al[mt], Bh[nt][1], Bh[nt][3]);
                }
        }
    };

    #pragma unroll
    for (int i = 0; i < 2; ++i) {
        const int e = i * 512 + tid;
        if (e < 768) {
            const int c = e - (e >= 384 ? 384 : 0);
            sr[e] = g_r[(size_t)(e >= 384 ? bt1 : bt0) * COUT + s * CIN + c];
        }
    }
    ldB(0, 0); CP_COMMIT();
    ldB(64, 1); CP_COMMIT();
    ldB(128, 2); CP_COMMIT();
    ldgA(0);
    __syncthreads();
    stsA(0, 0);
    ldgA(64);

    #pragma unroll 1
    for (int kc = 0; kc < 6; ++kc) {
        CP_WAIT2();
        __syncthreads();
        if (kc < 3) ldB((kc + 3) * 64, (kc + 3) & 3);
        CP_COMMIT();
        if (kc < 5) {
            stsA((kc + 1) * 64, (kc + 1) & 1);
            if (kc < 4) ldgA((kc + 2) * 64);
        }
        compute(kc & 1, kc & 3);
    }

    #pragma unroll
    for (int mt = 0; mt < 2; ++mt)
        #pragma unroll
        for (int rh = 0; rh < 2; ++rh) {
            const int m = mBase + wm + mt * 16 + (lane >> 2) + rh * 8;
            const int bt = m / NTOK;
            const int n = m - bt * NTOK;
            float* op = out + (size_t)bt * OUT_BT_STRIDE + n;
            const float* rr = g_r + (size_t)bt * COUT + oBase + wn;
            const float* bb = bias + oBase + wn;
            #pragma unroll
            for (int nt2 = 0; nt2 < 4; ++nt2) {
                const int c0 = nt2 * 8 + (lane & 3) * 2;
                const float v0 = acc[mt][nt2][rh * 2 + 0] + bb[c0] * rr[c0];
                const float v1 = acc[mt][nt2][rh * 2 + 1] + bb[c0 + 1] * rr[c0 + 1];
                op[(size_t)(oBase + wn + c0) * NTOK] = v0;
                op[(size_t)(oBase + wn + c0 + 1) * NTOK] = v1;
            }
        }
}

// ======================= launch =======================
extern "C" void kernel_launch(void* const* d_in, const int* in_sizes, int n_in,
                              void* d_out, int out_size) {
    const float* x = (const float*)d_in[0];
    const float* rf_w = (const float*)d_in[1];
    const float* rf_b = (const float*)d_in[2];
    const float* moe_w = (const float*)d_in[3];
    const float* moe_b = (const float*)d_in[4];
    const float* weight = (const float*)d_in[5];
    const float* bias = (const float*)d_in[6];
    float* out = (float*)d_out;

    cudaFuncSetAttribute(k_main, cudaFuncAttributeMaxDynamicSharedMemorySize, SMEM_MAIN);
    cudaFuncSetAttribute(k_routing, cudaFuncAttributeMaxDynamicSharedMemorySize, 61440);

    k_rf<<<32, 128>>>(x, rf_w, rf_b);
    k_prep<<<216 + 5184, 256>>>(weight, moe_w);
    k_routing<<<dim3(144, 8), 256, 61440>>>(x, moe_b);
    k_main<<<dim3(9, 394), 512, SMEM_MAIN>>>(x, bias, out);
}

// round 15
// speedup vs baseline: 1.0166x; 1.0166x over previous
#include <cuda_runtime.h>
#include <cuda_fp16.h>
#include <cstdint>

#define NTOK 197
#define CIN 384
#define COUT 1152
#define TT 8
#define OUT_BT_STRIDE (COUT * NTOK)

__device__ float g_rf[32 * 4];
__device__ float g_r[256 * COUT];
__device__ uint4 g_wh4[COUT * CIN / 8];    // weight fp16, [o][k] row-major
__device__ float g_mw[4 * 3 * COUT * CIN]; // moe_w transposed: [e][k][o][c]

// ======================= helpers =======================
__device__ __forceinline__ uint32_t smem_u32(const void* p) {
    uint32_t a;
    asm("{ .reg .u64 t; cvta.to.shared.u64 t, %1; cvt.u32.u64 %0, t; }" : "=r"(a) : "l"(p));
    return a;
}
__device__ __forceinline__ uint32_t hsplit2(float a, float b, uint32_t& lo) {
    __half2 h = __floats2half2_rn(a, b);
    float2 hf = __half22float2(h);
    __half2 l = __floats2half2_rn(a - hf.x, b - hf.y);
    lo = *reinterpret_cast<uint32_t*>(&l);
    return *reinterpret_cast<uint32_t*>(&h);
}
__device__ __forceinline__ uint32_t h2pack(float a, float b) {
    __half2 h = __floats2half2_rn(a, b);
    return *reinterpret_cast<uint32_t*>(&h);
}
#define STS128(a, v0, v1, v2, v3) \
    asm volatile("st.shared.v4.b32 [%0], {%1, %2, %3, %4};" :: "r"(a), "r"(v0), "r"(v1), "r"(v2), "r"(v3) : "memory")
#define CP16(dst, src) \
    asm volatile("cp.async.cg.shared.global [%0], [%1], 16;" :: "r"(dst), "l"(src) : "memory")
#define CP_COMMIT() asm volatile("cp.async.commit_group;" ::: "memory")
#define CP_WAIT2() asm volatile("cp.async.wait_group 2;" ::: "memory")
#define LDSM4(r, a)                                                                   \
    asm volatile("ldmatrix.sync.aligned.m8n8.x4.shared.b16 {%0,%1,%2,%3}, [%4];"      \
        : "=r"((r)[0]), "=r"((r)[1]), "=r"((r)[2]), "=r"((r)[3]) : "r"(a))
#define MMA16816(d, a, b0, b1)                                                        \
    asm("mma.sync.aligned.m16n8k16.row.col.f32.f16.f16.f32 "                          \
        "{%0,%1,%2,%3}, {%4,%5,%6,%7}, {%8,%9}, {%0,%1,%2,%3};"                       \
        : "+f"((d)[0]), "+f"((d)[1]), "+f"((d)[2]), "+f"((d)[3])                      \
        : "r"((a)[0]), "r"((a)[1]), "r"((a)[2]), "r"((a)[3]), "r"(b0), "r"(b1))

// ============ Kernel 0: prep (weight cvt + moe_w transpose + rf, fused) ============
// blocks [0,216):   weight -> g_wh4 (fp16)
// blocks [216,792): moe_w [e][o][c][k] -> g_mw [e][k][o][c], smem tile transpose
// blocks [792,824): rf[b][e] = mean_t(cls) @ rf_w^T + rf_b
__global__ __launch_bounds__(256) void k_prep(const float* __restrict__ w,
                                              const float* __restrict__ moe_w,
                                              const float* __restrict__ x,
                                              const float* __restrict__ rf_w,
                                              const float* __restrict__ rf_b) {
    __shared__ float tsm[8 * 1152];           // 36 KB transpose tile
    __shared__ float red[4][256];
    const int bx = blockIdx.x;
    const int tid = threadIdx.x;

    if (bx < 216) {
        int i = bx * 256 + tid;
        const float4 v0 = reinterpret_cast<const float4*>(w)[i * 2];
        const float4 v1 = reinterpret_cast<const float4*>(w)[i * 2 + 1];
        g_wh4[i] = make_uint4(h2pack(v0.x, v0.y), h2pack(v0.z, v0.w),
                              h2pack(v1.x, v1.y), h2pack(v1.z, v1.w));
    } else if (bx < 792) {
        const int idx = bx - 216;
        const int e = idx / 144;
        const int o0 = (idx - e * 144) * 8;
        const float* src = moe_w + (size_t)(e * COUT + o0) * CIN * 3;  // 9216 floats
        #pragma unroll
        for (int it = 0; it < 36; ++it)
            tsm[it * 256 + tid] = src[it * 256 + tid];                 // coalesced
        __syncthreads();
        #pragma unroll
        for (int it = 0; it < 36; ++it) {
            const int j = it * 256 + tid;      // k = j/3072, o = (j%3072)/384, c = j%384
            const int k = j / 3072;
            const int r2 = j - k * 3072;
            const int o = r2 / 384;
            const int c = r2 - o * 384;
            // coalesced write (c fastest); smem read stride 3 (conflict-free)
            g_mw[((size_t)(e * 3 + k) * COUT + o0 + o) * CIN + c] = tsm[o * 1152 + c * 3 + k];
        }
    } else {
        const int b = bx - 792;
        float a0 = 0.f, a1 = 0.f, a2 = 0.f, a3 = 0.f;
        for (int c = tid; c < CIN; c += 256) {
            float p = 0.f;
            #pragma unroll
            for (int t = 0; t < TT; ++t)
                p += x[(size_t)(b * TT + t) * NTOK * CIN + c];
            p *= 0.125f;
            a0 += p * rf_w[0 * CIN + c];
            a1 += p * rf_w[1 * CIN + c];
            a2 += p * rf_w[2 * CIN + c];
            a3 += p * rf_w[3 * CIN + c];
        }
        red[0][tid] = a0; red[1][tid] = a1; red[2][tid] = a2; red[3][tid] = a3;
        __syncthreads();
        for (int s = 128; s > 0; s >>= 1) {
            if (tid < s) {
                red[0][tid] += red[0][tid + s];
                red[1][tid] += red[1][tid + s];
                red[2][tid] += red[2][tid + s];
                red[3][tid] += red[3][tid + s];
            }
            __syncthreads();
        }
        if (tid < 4) g_rf[b * 4 + tid] = red[tid][0] + rf_b[tid];
    }
}

// ======================= Kernel 1: routing (coalesced g_mw) =======================
__global__ __launch_bounds__(256) void k_routing(const float* __restrict__ x,
                                                 const float* __restrict__ moe_b) {
    extern __shared__ float rsm[];            // clsp[4][384][10]
    __shared__ float srf[16];
    const int tid = threadIdx.x, lane = tid & 31, wid = tid >> 5;
    const int o = blockIdx.x * 8 + wid;
    const int b0 = blockIdx.y * 4;

    if (tid < 16) srf[tid] = g_rf[(b0 + (tid >> 2)) * 4 + (tid & 3)];
    #pragma unroll 1
    for (int it = 0; it < 48; ++it) {
        int e = it * 256 + tid;
        int bi = e / 3072;
        int r2 = e - bi * 3072;
        int t = r2 / CIN;
        int c = r2 - t * CIN;
        rsm[bi * 3840 + c * 10 + t + 1] =
            x[(size_t)((b0 + bi) * TT + t) * NTOK * CIN + c];
    }
    #pragma unroll 1
    for (int it = 0; it < 12; ++it) {
        int e = it * 256 + tid;
        int bi = e / 768;
        int r2 = e - bi * 768;
        int c = r2 >> 1;
        rsm[bi * 3840 + c * 10 + (r2 & 1) * 9] = 0.f;
    }
    __syncthreads();

    float f[16];
    #pragma unroll
    for (int i = 0; i < 16; ++i) f[i] = srf[i];

    float vals[32];
    #pragma unroll
    for (int i = 0; i < 32; ++i) vals[i] = 0.f;

    const float* wb[12];
    #pragma unroll
    for (int ek = 0; ek < 12; ++ek)
        wb[ek] = g_mw + (size_t)(ek * COUT + o) * CIN + lane;

    #pragma unroll 1
    for (int ci = 0; ci < 12; ++ci) {
        const int c = ci * 32;
        float w[4][3];
        #pragma unroll
        for (int e = 0; e < 4; ++e)
            #pragma unroll
            for (int k = 0; k < 3; ++k)
                w[e][k] = wb[e * 3 + k][c];   // fully coalesced (lane = c offset)
        #pragma unroll
        for (int bi = 0; bi < 4; ++bi) {
            const float f0 = f[bi * 4 + 0], f1 = f[bi * 4 + 1];
            const float f2 = f[bi * 4 + 2], f3 = f[bi * 4 + 3];
            const float wv0 = f0 * w[0][0] + f1 * w[1][0] + f2 * w[2][0] + f3 * w[3][0];
            const float wv1 = f0 * w[0][1] + f1 * w[1][1] + f2 * w[2][1] + f3 * w[3][1];
            const float wv2 = f0 * w[0][2] + f1 * w[1][2] + f2 * w[2][2] + f3 * w[3][2];
            const float* cl = rsm + bi * 3840 + (c + lane) * 10;
            float cv[10];
            #pragma unroll
            for (int t = 0; t < 10; ++t) cv[t] = cl[t];
            #pragma unroll
            for (int t = 0; t < TT; ++t)
                vals[bi * 8 + t] += wv0 * cv[t] + wv1 * cv[t + 1] + wv2 * cv[t + 2];
        }
    }

    int cnt = 32;
    #pragma unroll
    for (int off = 16; off; off >>= 1) {
        cnt >>= 1;
        #pragma unroll 16
        for (int j = 0; j < cnt; ++j) {
            const float send = (lane & off) ? vals[j] : vals[j + cnt];
            const float other = __shfl_xor_sync(0xffffffffu, send, off);
            vals[j] = ((lane & off) ? vals[j + cnt] : vals[j]) + other;
        }
    }
    {
        const int bi = lane >> 3, t = lane & 7;
        float bo = 1.0f;
        #pragma unroll
        for (int e = 0; e < 4; ++e) bo += f[bi * 4 + e] * moe_b[e * COUT + o];
        g_r[(size_t)((b0 + bi) * TT + t) * COUT + o] = vals[0] + bo;
    }
}

// ======================= Kernel 2: main mma.sync GEMM (R12, unchanged) =======================
#define A_STRIDE 32768
#define OFF_B 65536
#define B_STRIDE 16384
#define OFF_SR 131072
#define SMEM_MAIN (OFF_SR + 3072 + 1024)

__global__ __launch_bounds__(512, 1) void k_main(const float* __restrict__ x,
                                                 const float* __restrict__ bias,
                                                 float* __restrict__ out) {
    extern __shared__ char dsm[];
    const uint32_t sb = (smem_u32(dsm) + 1023u) & ~1023u;
    char* dsm_al = dsm + (sb - smem_u32(dsm));
    float* sr = reinterpret_cast<float*>(dsm_al + OFF_SR);
    const int tid = threadIdx.x, lane = tid & 31, wid = tid >> 5;
    const int oBase = blockIdx.x * 128;
    const int s = blockIdx.x / 3;
    const int mBase = blockIdx.y * 128;
    const int bt0 = mBase / NTOK;
    const int bt1 = (mBase + 127) / NTOK;

    const int arow = tid >> 2;
    const int aq = tid & 3;
    const int am = mBase + arow;
    const int abt = am / NTOK;
    const float* axp = x + (size_t)am * CIN + aq * 16;
    const float* srow = sr + (abt != bt0 ? 384 : 0) + aq * 16;

    uint32_t sA[2];
    {
        const uint32_t xm = (uint32_t)(arow & 7) * 16;
        #pragma unroll
        for (int g = 0; g < 2; ++g)
            sA[g] = (uint32_t)arow * 128 + (((uint32_t)(aq * 32 + g * 16)) ^ xm);
    }

    const int wm = (wid & 3) * 32;
    const int wn = (wid >> 2) * 32;

    const int lrow = lane & 15, lkh = lane >> 4;
    uint32_t aBase[2], aXm[2], bBase[2], bXm[2];
    #pragma unroll
    for (int mt = 0; mt < 2; ++mt) {
        const int row = wm + mt * 16 + lrow;
        aBase[mt] = (uint32_t)row * 128;
        aXm[mt] = (uint32_t)(row & 7) * 16;
    }
    #pragma unroll
    for (int nt = 0; nt < 2; ++nt) {
        const int row = wn + nt * 16 + lrow;
        bBase[nt] = (uint32_t)row * 128;
        bXm[nt] = (uint32_t)(row & 7) * 16;
    }

    float acc[2][4][4];
    #pragma unroll
    for (int i = 0; i < 2; ++i)
        #pragma unroll
        for (int j = 0; j < 4; ++j)
            #pragma unroll
            for (int e = 0; e < 4; ++e) acc[i][j][e] = 0.f;

    float4 xr[4];

    auto ldgA = [&](int kOff) {
        const float4* xp4 = reinterpret_cast<const float4*>(axp + kOff);
        #pragma unroll
        for (int i = 0; i < 4; ++i) xr[i] = xp4[i];
    };
    auto stsA = [&](int kOff, int buf) {
        const float4* rp4 = reinterpret_cast<const float4*>(srow + kOff);
        const uint32_t aH = sb + buf * A_STRIDE;
        #pragma unroll
        for (int g = 0; g < 2; ++g) {
            const float4 xa = xr[2 * g], xb = xr[2 * g + 1];
            const float4 ra = rp4[2 * g], rb = rp4[2 * g + 1];
            uint32_t h[4], l[4];
            h[0] = hsplit2(xa.x * ra.x, xa.y * ra.y, l[0]);
            h[1] = hsplit2(xa.z * ra.z, xa.w * ra.w, l[1]);
            h[2] = hsplit2(xb.x * rb.x, xb.y * rb.y, l[2]);
            h[3] = hsplit2(xb.z * rb.z, xb.w * rb.w, l[3]);
            STS128(aH + sA[g], h[0], h[1], h[2], h[3]);
            STS128(aH + sA[g] + 16384, l[0], l[1], l[2], l[3]);
        }
    };
    auto ldB = [&](int kOff, int buf) {
        const uint32_t bH = sb + OFF_B + buf * B_STRIDE;
        const char* gh = (const char*)g_wh4;
        #pragma unroll
        for (int it = 0; it < 2; ++it) {
            const int idx = it * 512 + tid;
            const int ol = idx >> 3;
            const int kq = idx & 7;
            const size_t gb = ((size_t)(oBase + ol) * CIN + kOff + kq * 8) * 2;
            const uint32_t off = (uint32_t)(ol * 128) +
                                 (((uint32_t)(kq * 16)) ^ ((uint32_t)(ol & 7) * 16));
            CP16(bH + off, gh + gb);
        }
    };
    auto compute = [&](int bufA, int bufB) {
        const uint32_t baseA = sb + bufA * A_STRIDE;
        const uint32_t baseB = sb + OFF_B + bufB * B_STRIDE;
        #pragma unroll
        for (int kk = 0; kk < 4; ++kk) {
            const uint32_t kbl = (uint32_t)(kk * 32 + lkh * 16);
            uint32_t Ah[2][4], Al[2][4], Bh[2][4];
            #pragma unroll
            for (int mt = 0; mt < 2; ++mt) {
                const uint32_t ad = baseA + aBase[mt] + (kbl ^ aXm[mt]);
                LDSM4(Ah[mt], ad);
                LDSM4(Al[mt], ad + 16384);
            }
            #pragma unroll
            for (int nt = 0; nt < 2; ++nt) {
                const uint32_t bd = baseB + bBase[nt] + (kbl ^ bXm[nt]);
                LDSM4(Bh[nt], bd);
            }
            #pragma unroll
            for (int nt = 0; nt < 2; ++nt)
                #pragma unroll
                for (int mt = 0; mt < 2; ++mt) {
                    MMA16816(acc[mt][nt * 2],     Ah[mt], Bh[nt][0], Bh[nt][2]);
                    MMA16816(acc[mt][nt * 2 + 1], Ah[mt], Bh[nt][1], Bh[nt][3]);
                }
            #pragma unroll
            for (int nt = 0; nt < 2; ++nt)
                #pragma unroll
                for (int mt = 0; mt < 2; ++mt) {
                    MMA16816(acc[mt][nt * 2],     Al[mt], Bh[nt][0], Bh[nt][2]);
                    MMA16816(acc[mt][nt * 2 + 1], Al[mt], Bh[nt][1], Bh[nt][3]);
                }
        }
    };

    #pragma unroll
    for (int i = 0; i < 2; ++i) {
        const int e = i * 512 + tid;
        if (e < 768) {
            const int c = e - (e >= 384 ? 384 : 0);
            sr[e] = g_r[(size_t)(e >= 384 ? bt1 : bt0) * COUT + s * CIN + c];
        }
    }
    ldB(0, 0); CP_COMMIT();
    ldB(64, 1); CP_COMMIT();
    ldB(128, 2); CP_COMMIT();
    ldgA(0);
    __syncthreads();
    stsA(0, 0);
    ldgA(64);

    #pragma unroll 1
    for (int kc = 0; kc < 6; ++kc) {
        CP_WAIT2();
        __syncthreads();
        if (kc < 3) ldB((kc + 3) * 64, (kc + 3) & 3);
        CP_COMMIT();
        if (kc < 5) {
            stsA((kc + 1) * 64, (kc + 1) & 1);
            if (kc < 4) ldgA((kc + 2) * 64);
        }
        compute(kc & 1, kc & 3);
    }

    #pragma unroll
    for (int mt = 0; mt < 2; ++mt)
        #pragma unroll
        for (int rh = 0; rh < 2; ++rh) {
            const int m = mBase + wm + mt * 16 + (lane >> 2) + rh * 8;
            const int bt = m / NTOK;
            const int n = m - bt * NTOK;
            float* op = out + (size_t)bt * OUT_BT_STRIDE + n;
            const float* rr = g_r + (size_t)bt * COUT + oBase + wn;
            const float* bb = bias + oBase + wn;
            #pragma unroll
            for (int nt2 = 0; nt2 < 4; ++nt2) {
                const int c0 = nt2 * 8 + (lane & 3) * 2;
                const float v0 = acc[mt][nt2][rh * 2 + 0] + bb[c0] * rr[c0];
                const float v1 = acc[mt][nt2][rh * 2 + 1] + bb[c0 + 1] * rr[c0 + 1];
                op[(size_t)(oBase + wn + c0) * NTOK] = v0;
                op[(size_t)(oBase + wn + c0 + 1) * NTOK] = v1;
            }
        }
}

// ======================= launch =======================
extern "C" void kernel_launch(void* const* d_in, const int* in_sizes, int n_in,
                              void* d_out, int out_size) {
    const float* x = (const float*)d_in[0];
    const float* rf_w = (const float*)d_in[1];
    const float* rf_b = (const float*)d_in[2];
    const float* moe_w = (const float*)d_in[3];
    const float* moe_b = (const float*)d_in[4];
    const float* weight = (const float*)d_in[5];
    const float* bias = (const float*)d_in[6];
    float* out = (float*)d_out;

    cudaFuncSetAttribute(k_main, cudaFuncAttributeMaxDynamicSharedMemorySize, SMEM_MAIN);
    cudaFuncSetAttribute(k_routing, cudaFuncAttributeMaxDynamicSharedMemorySize, 61440);

    k_prep<<<824, 256>>>(weight, moe_w, x, rf_w, rf_b);
    k_routing<<<dim3(144, 8), 256, 61440>>>(x, moe_b);
    k_main<<<dim3(9, 394), 512, SMEM_MAIN>>>(x, bias, out);
}

// round 16
// speedup vs baseline: 1.2638x; 1.2432x over previous
#include <cuda_runtime.h>
#include <cuda_fp16.h>
#include <cstdint>

#define NTOK 197
#define CIN 384
#define COUT 1152
#define TT 8
#define OUT_BT_STRIDE (COUT * NTOK)

__device__ float g_rf[32 * 4];
__device__ float g_r[256 * COUT];
__device__ uint4 g_wh4[COUT * CIN / 8];    // weight fp16, [o][k] row-major
__device__ float g_mw[4 * 3 * COUT * CIN]; // moe_w transposed: [e][k][o][c]

// ======================= helpers =======================
__device__ __forceinline__ uint32_t smem_u32(const void* p) {
    uint32_t a;
    asm("{ .reg .u64 t; cvta.to.shared.u64 t, %1; cvt.u32.u64 %0, t; }" : "=r"(a) : "l"(p));
    return a;
}
__device__ __forceinline__ uint32_t h2pack(float a, float b) {
    __half2 h = __floats2half2_rn(a, b);
    return *reinterpret_cast<uint32_t*>(&h);
}
#define STS128(a, v0, v1, v2, v3) \
    asm volatile("st.shared.v4.b32 [%0], {%1, %2, %3, %4};" :: "r"(a), "r"(v0), "r"(v1), "r"(v2), "r"(v3) : "memory")
#define CP16(dst, src) \
    asm volatile("cp.async.cg.shared.global [%0], [%1], 16;" :: "r"(dst), "l"(src) : "memory")
#define CP_COMMIT() asm volatile("cp.async.commit_group;" ::: "memory")
#define CP_WAIT2() asm volatile("cp.async.wait_group 2;" ::: "memory")
#define LDSM4(r, a)                                                                   \
    asm volatile("ldmatrix.sync.aligned.m8n8.x4.shared.b16 {%0,%1,%2,%3}, [%4];"      \
        : "=r"((r)[0]), "=r"((r)[1]), "=r"((r)[2]), "=r"((r)[3]) : "r"(a))
#define MMA16816(d, a, b0, b1)                                                        \
    asm("mma.sync.aligned.m16n8k16.row.col.f32.f16.f16.f32 "                          \
        "{%0,%1,%2,%3}, {%4,%5,%6,%7}, {%8,%9}, {%0,%1,%2,%3};"                       \
        : "+f"((d)[0]), "+f"((d)[1]), "+f"((d)[2]), "+f"((d)[3])                      \
        : "r"((a)[0]), "r"((a)[1]), "r"((a)[2]), "r"((a)[3]), "r"(b0), "r"(b1))

// ============ Kernel 0: prep (weight cvt + moe_w transpose + rf, fused) ============
__global__ __launch_bounds__(256) void k_prep(const float* __restrict__ w,
                                              const float* __restrict__ moe_w,
                                              const float* __restrict__ x,
                                              const float* __restrict__ rf_w,
                                              const float* __restrict__ rf_b) {
    __shared__ float tsm[8 * 1152];           // 36 KB transpose tile
    __shared__ float red[4][256];
    const int bx = blockIdx.x;
    const int tid = threadIdx.x;

    if (bx < 216) {
        int i = bx * 256 + tid;
        const float4 v0 = reinterpret_cast<const float4*>(w)[i * 2];
        const float4 v1 = reinterpret_cast<const float4*>(w)[i * 2 + 1];
        g_wh4[i] = make_uint4(h2pack(v0.x, v0.y), h2pack(v0.z, v0.w),
                              h2pack(v1.x, v1.y), h2pack(v1.z, v1.w));
    } else if (bx < 792) {
        const int idx = bx - 216;
        const int e = idx / 144;
        const int o0 = (idx - e * 144) * 8;
        const float* src = moe_w + (size_t)(e * COUT + o0) * CIN * 3;  // 9216 floats
        #pragma unroll
        for (int it = 0; it < 36; ++it)
            tsm[it * 256 + tid] = src[it * 256 + tid];                 // coalesced
        __syncthreads();
        #pragma unroll
        for (int it = 0; it < 36; ++it) {
            const int j = it * 256 + tid;
            const int k = j / 3072;
            const int r2 = j - k * 3072;
            const int o = r2 / 384;
            const int c = r2 - o * 384;
            g_mw[((size_t)(e * 3 + k) * COUT + o0 + o) * CIN + c] = tsm[o * 1152 + c * 3 + k];
        }
    } else {
        const int b = bx - 792;
        float a0 = 0.f, a1 = 0.f, a2 = 0.f, a3 = 0.f;
        for (int c = tid; c < CIN; c += 256) {
            float p = 0.f;
            #pragma unroll
            for (int t = 0; t < TT; ++t)
                p += x[(size_t)(b * TT + t) * NTOK * CIN + c];
            p *= 0.125f;
            a0 += p * rf_w[0 * CIN + c];
            a1 += p * rf_w[1 * CIN + c];
            a2 += p * rf_w[2 * CIN + c];
            a3 += p * rf_w[3 * CIN + c];
        }
        red[0][tid] = a0; red[1][tid] = a1; red[2][tid] = a2; red[3][tid] = a3;
        __syncthreads();
        for (int s = 128; s > 0; s >>= 1) {
            if (tid < s) {
                red[0][tid] += red[0][tid + s];
                red[1][tid] += red[1][tid + s];
                red[2][tid] += red[2][tid + s];
                red[3][tid] += red[3][tid + s];
            }
            __syncthreads();
        }
        if (tid < 4) g_rf[b * 4 + tid] = red[tid][0] + rf_b[tid];
    }
}

// ======================= Kernel 1: routing (coalesced g_mw, stride-11 smem) ===========
__global__ __launch_bounds__(256) void k_routing(const float* __restrict__ x,
                                                 const float* __restrict__ moe_b) {
    extern __shared__ float rsm[];            // clsp[4][384][11] (stride 11: conflict-free)
    __shared__ float srf[16];
    const int tid = threadIdx.x, lane = tid & 31, wid = tid >> 5;
    const int o = blockIdx.x * 8 + wid;
    const int b0 = blockIdx.y * 4;

    if (tid < 16) srf[tid] = g_rf[(b0 + (tid >> 2)) * 4 + (tid & 3)];
    #pragma unroll 1
    for (int it = 0; it < 48; ++it) {
        int e = it * 256 + tid;
        int bi = e / 3072;
        int r2 = e - bi * 3072;
        int t = r2 / CIN;
        int c = r2 - t * CIN;
        rsm[bi * 4224 + c * 11 + t + 1] =
            x[(size_t)((b0 + bi) * TT + t) * NTOK * CIN + c];
    }
    #pragma unroll 1
    for (int it = 0; it < 12; ++it) {
        int e = it * 256 + tid;
        int bi = e / 768;
        int r2 = e - bi * 768;
        int c = r2 >> 1;
        rsm[bi * 4224 + c * 11 + (r2 & 1) * 9] = 0.f;
    }
    __syncthreads();

    float f[16];
    #pragma unroll
    for (int i = 0; i < 16; ++i) f[i] = srf[i];

    float vals[32];
    #pragma unroll
    for (int i = 0; i < 32; ++i) vals[i] = 0.f;

    const float* wb[12];
    #pragma unroll
    for (int ek = 0; ek < 12; ++ek)
        wb[ek] = g_mw + (size_t)(ek * COUT + o) * CIN + lane;

    #pragma unroll 1
    for (int ci = 0; ci < 12; ++ci) {
        const int c = ci * 32;
        float w[4][3];
        #pragma unroll
        for (int e = 0; e < 4; ++e)
            #pragma unroll
            for (int k = 0; k < 3; ++k)
                w[e][k] = wb[e * 3 + k][c];   // fully coalesced
        #pragma unroll
        for (int bi = 0; bi < 4; ++bi) {
            const float f0 = f[bi * 4 + 0], f1 = f[bi * 4 + 1];
            const float f2 = f[bi * 4 + 2], f3 = f[bi * 4 + 3];
            const float wv0 = f0 * w[0][0] + f1 * w[1][0] + f2 * w[2][0] + f3 * w[3][0];
            const float wv1 = f0 * w[0][1] + f1 * w[1][1] + f2 * w[2][1] + f3 * w[3][1];
            const float wv2 = f0 * w[0][2] + f1 * w[1][2] + f2 * w[2][2] + f3 * w[3][2];
            const float* cl = rsm + bi * 4224 + (c + lane) * 11;
            float cv[10];
            #pragma unroll
            for (int t = 0; t < 10; ++t) cv[t] = cl[t];
            #pragma unroll
            for (int t = 0; t < TT; ++t)
                vals[bi * 8 + t] += wv0 * cv[t] + wv1 * cv[t + 1] + wv2 * cv[t + 2];
        }
    }

    int cnt = 32;
    #pragma unroll
    for (int off = 16; off; off >>= 1) {
        cnt >>= 1;
        #pragma unroll 16
        for (int j = 0; j < cnt; ++j) {
            const float send = (lane & off) ? vals[j] : vals[j + cnt];
            const float other = __shfl_xor_sync(0xffffffffu, send, off);
            vals[j] = ((lane & off) ? vals[j + cnt] : vals[j]) + other;
        }
    }
    {
        const int bi = lane >> 3, t = lane & 7;
        float bo = 1.0f;
        #pragma unroll
        for (int e = 0; e < 4; ++e) bo += f[bi * 4 + e] * moe_b[e * COUT + o];
        g_r[(size_t)((b0 + bi) * TT + t) * COUT + o] = vals[0] + bo;
    }
}

// ======================= Kernel 2: main GEMM — single-pass fp16 =======================
// D = fp16(x*r) * fp16(W). CTA 128m x 128o, 512 thr, 16 warps (4m x 4n, 32x32).
// K=384 in 6 chunks of 64. R12 pipeline: A 2-stage, B 4-stage cp.async ring.
#define A_STRIDE 16384
#define OFF_B 32768
#define B_STRIDE 16384
#define OFF_SR 98304
#define SMEM_MAIN (OFF_SR + 3072 + 1024)

__global__ __launch_bounds__(512, 1) void k_main(const float* __restrict__ x,
                                                 const float* __restrict__ bias,
                                                 float* __restrict__ out) {
    extern __shared__ char dsm[];
    const uint32_t sb = (smem_u32(dsm) + 1023u) & ~1023u;
    char* dsm_al = dsm + (sb - smem_u32(dsm));
    float* sr = reinterpret_cast<float*>(dsm_al + OFF_SR);
    const int tid = threadIdx.x, lane = tid & 31, wid = tid >> 5;
    const int oBase = blockIdx.x * 128;
    const int s = blockIdx.x / 3;
    const int mBase = blockIdx.y * 128;
    const int bt0 = mBase / NTOK;
    const int bt1 = (mBase + 127) / NTOK;

    const int arow = tid >> 2;
    const int aq = tid & 3;
    const int am = mBase + arow;
    const int abt = am / NTOK;
    const float* axp = x + (size_t)am * CIN + aq * 16;
    const float* srow = sr + (abt != bt0 ? 384 : 0) + aq * 16;

    uint32_t sA[2];
    {
        const uint32_t xm = (uint32_t)(arow & 7) * 16;
        #pragma unroll
        for (int g = 0; g < 2; ++g)
            sA[g] = (uint32_t)arow * 128 + (((uint32_t)(aq * 32 + g * 16)) ^ xm);
    }

    const int wm = (wid & 3) * 32;
    const int wn = (wid >> 2) * 32;

    const int lrow = lane & 15, lkh = lane >> 4;
    uint32_t aBase[2], aXm[2], bBase[2], bXm[2];
    #pragma unroll
    for (int mt = 0; mt < 2; ++mt) {
        const int row = wm + mt * 16 + lrow;
        aBase[mt] = (uint32_t)row * 128;
        aXm[mt] = (uint32_t)(row & 7) * 16;
    }
    #pragma unroll
    for (int nt = 0; nt < 2; ++nt) {
        const int row = wn + nt * 16 + lrow;
        bBase[nt] = (uint32_t)row * 128;
        bXm[nt] = (uint32_t)(row & 7) * 16;
    }

    float acc[2][4][4];
    #pragma unroll
    for (int i = 0; i < 2; ++i)
        #pragma unroll
        for (int j = 0; j < 4; ++j)
            #pragma unroll
            for (int e = 0; e < 4; ++e) acc[i][j][e] = 0.f;

    float4 xr[4];

    auto ldgA = [&](int kOff) {
        const float4* xp4 = reinterpret_cast<const float4*>(axp + kOff);
        #pragma unroll
        for (int i = 0; i < 4; ++i) xr[i] = xp4[i];
    };
    auto stsA = [&](int kOff, int buf) {
        const float4* rp4 = reinterpret_cast<const float4*>(srow + kOff);
        const uint32_t aH = sb + buf * A_STRIDE;
        #pragma unroll
        for (int g = 0; g < 2; ++g) {
            const float4 xa = xr[2 * g], xb = xr[2 * g + 1];
            const float4 ra = rp4[2 * g], rb = rp4[2 * g + 1];
            const uint32_t h0 = h2pack(xa.x * ra.x, xa.y * ra.y);
            const uint32_t h1 = h2pack(xa.z * ra.z, xa.w * ra.w);
            const uint32_t h2 = h2pack(xb.x * rb.x, xb.y * rb.y);
            const uint32_t h3 = h2pack(xb.z * rb.z, xb.w * rb.w);
            STS128(aH + sA[g], h0, h1, h2, h3);
        }
    };
    auto ldB = [&](int kOff, int buf) {
        const uint32_t bH = sb + OFF_B + buf * B_STRIDE;
        const char* gh = (const char*)g_wh4;
        #pragma unroll
        for (int it = 0; it < 2; ++it) {
            const int idx = it * 512 + tid;
            const int ol = idx >> 3;
            const int kq = idx & 7;
            const size_t gb = ((size_t)(oBase + ol) * CIN + kOff + kq * 8) * 2;
            const uint32_t off = (uint32_t)(ol * 128) +
                                 (((uint32_t)(kq * 16)) ^ ((uint32_t)(ol & 7) * 16));
            CP16(bH + off, gh + gb);
        }
    };
    auto compute = [&](int bufA, int bufB) {
        const uint32_t baseA = sb + bufA * A_STRIDE;
        const uint32_t baseB = sb + OFF_B + bufB * B_STRIDE;
        #pragma unroll
        for (int kk = 0; kk < 4; ++kk) {
            const uint32_t kbl = (uint32_t)(kk * 32 + lkh * 16);
            uint32_t Ah[2][4], Bh[2][4];
            #pragma unroll
            for (int mt = 0; mt < 2; ++mt) {
                const uint32_t ad = baseA + aBase[mt] + (kbl ^ aXm[mt]);
                LDSM4(Ah[mt], ad);
            }
            #pragma unroll
            for (int nt = 0; nt < 2; ++nt) {
                const uint32_t bd = baseB + bBase[nt] + (kbl ^ bXm[nt]);
                LDSM4(Bh[nt], bd);
            }
            #pragma unroll
            for (int nt = 0; nt < 2; ++nt)
                #pragma unroll
                for (int mt = 0; mt < 2; ++mt) {
                    MMA16816(acc[mt][nt * 2],     Ah[mt], Bh[nt][0], Bh[nt][2]);
                    MMA16816(acc[mt][nt * 2 + 1], Ah[mt], Bh[nt][1], Bh[nt][3]);
                }
        }
    };

    #pragma unroll
    for (int i = 0; i < 2; ++i) {
        const int e = i * 512 + tid;
        if (e < 768) {
            const int c = e - (e >= 384 ? 384 : 0);
            sr[e] = g_r[(size_t)(e >= 384 ? bt1 : bt0) * COUT + s * CIN + c];
        }
    }
    ldB(0, 0); CP_COMMIT();
    ldB(64, 1); CP_COMMIT();
    ldB(128, 2); CP_COMMIT();
    ldgA(0);
    __syncthreads();
    stsA(0, 0);
    ldgA(64);

    #pragma unroll 1
    for (int kc = 0; kc < 6; ++kc) {
        CP_WAIT2();
        __syncthreads();
        if (kc < 3) ldB((kc + 3) * 64, (kc + 3) & 3);
        CP_COMMIT();
        if (kc < 5) {
            stsA((kc + 1) * 64, (kc + 1) & 1);
            if (kc < 4) ldgA((kc + 2) * 64);
        }
        compute(kc & 1, kc & 3);
    }

    #pragma unroll
    for (int mt = 0; mt < 2; ++mt)
        #pragma unroll
        for (int rh = 0; rh < 2; ++rh) {
            const int m = mBase + wm + mt * 16 + (lane >> 2) + rh * 8;
            const int bt = m / NTOK;
            const int n = m - bt * NTOK;
            float* op = out + (size_t)bt * OUT_BT_STRIDE + n;
            const float* rr = g_r + (size_t)bt * COUT + oBase + wn;
            const float* bb = bias + oBase + wn;
            #pragma unroll
            for (int nt2 = 0; nt2 < 4; ++nt2) {
                const int c0 = nt2 * 8 + (lane & 3) * 2;
                const float v0 = acc[mt][nt2][rh * 2 + 0] + bb[c0] * rr[c0];
                const float v1 = acc[mt][nt2][rh * 2 + 1] + bb[c0 + 1] * rr[c0 + 1];
                op[(size_t)(oBase + wn + c0) * NTOK] = v0;
                op[(size_t)(oBase + wn + c0 + 1) * NTOK] = v1;
            }
        }
}

// ======================= launch =======================
extern "C" void kernel_launch(void* const* d_in, const int* in_sizes, int n_in,
                              void* d_out, int out_size) {
    const float* x = (const float*)d_in[0];
    const float* rf_w = (const float*)d_in[1];
    const float* rf_b = (const float*)d_in[2];
    const float* moe_w = (const float*)d_in[3];
    const float* moe_b = (const float*)d_in[4];
    const float* weight = (const float*)d_in[5];
    const float* bias = (const float*)d_in[6];
    float* out = (float*)d_out;

    cudaFuncSetAttribute(k_main, cudaFuncAttributeMaxDynamicSharedMemorySize, SMEM_MAIN);
    cudaFuncSetAttribute(k_routing, cudaFuncAttributeMaxDynamicSharedMemorySize, 69632);

    k_prep<<<824, 256>>>(weight, moe_w, x, rf_w, rf_b);
    k_routing<<<dim3(144, 8), 256, 67584>>>(x, moe_b);
    k_main<<<dim3(9, 394), 512, SMEM_MAIN>>>(x, bias, out);
}